// round 1
// baseline (speedup 1.0000x reference)
#include <cuda_runtime.h>
#include <math.h>

// ---------------- problem constants ----------------
#define PLACE   31999
#define NB      8
#define STK     1024
#define SVV     256
#define HVV     1024
#define DD      1024
#define VV      32000
#define ROWS    8192      // NB*STK
#define VROWS   2048      // NB*SVV
#define NCH     25        // V chunks
#define CW      1280      // chunk width = 10 * 128
#define NROWT   64        // ROWS/128
#define LNEPS   1e-5f
#define TEMP    0.07f

// ---------------- scratch (device globals; no cudaMalloc allowed) ----------------
__device__ float g_mu[VROWS];
__device__ float g_rs[VROWS];
__device__ float g_vn[VROWS * HVV];       // normalized vis feats
__device__ float g_vp[VROWS * DD];        // vis_proj
__device__ int   g_src[ROWS];             // per-token source: >=0 embed id, <0 -> chunk -(src+1)
__device__ int   g_cnttxt[NB];
__device__ float g_text[ROWS * DD];       // text_emb
__device__ float g_pm[NCH * ROWS];        // per-chunk per-row max
__device__ float g_ps[NCH * ROWS];        // per-chunk per-row sumexp
__device__ float g_ll[ROWS];              // per-row (lse - label_logit)
__device__ float g_txtsum[NB * DD];
__device__ float g_vissum[NB * DD];

// ---------------- small helpers ----------------
__device__ __forceinline__ float4 ld4(const float* p) { return *(const float4*)p; }
__device__ __forceinline__ void st4(float* p, float4 v) { *(float4*)p = v; }

// ---------------- LN stats ----------------
__global__ void k_lnstats(const float* __restrict__ vis) {
    int r = blockIdx.x, t = threadIdx.x;
    __shared__ float sa[256], sb[256];
    float s = 0.f, s2 = 0.f;
    for (int i = t; i < HVV; i += 256) {
        float v = vis[(size_t)r * HVV + i];
        s += v; s2 += v * v;
    }
    sa[t] = s; sb[t] = s2; __syncthreads();
    for (int o = 128; o > 0; o >>= 1) {
        if (t < o) { sa[t] += sa[t + o]; sb[t] += sb[t + o]; }
        __syncthreads();
    }
    if (t == 0) {
        float mu = sa[0] / (float)HVV;
        float var = sb[0] / (float)HVV - mu * mu;
        g_mu[r] = mu;
        g_rs[r] = rsqrtf(var + LNEPS);
    }
}

// ---------------- LN apply ----------------
__global__ void k_lnapply(const float* __restrict__ vis,
                          const float* __restrict__ gamma,
                          const float* __restrict__ beta) {
    int r = blockIdx.x;
    int d0 = threadIdx.x * 4;
    float mu = g_mu[r], rs = g_rs[r];
    float4 x = ld4(vis + (size_t)r * HVV + d0);
    float4 g = ld4(gamma + d0);
    float4 b = ld4(beta + d0);
    float4 o;
    o.x = (x.x - mu) * rs * g.x + b.x;
    o.y = (x.y - mu) * rs * g.y + b.y;
    o.z = (x.z - mu) * rs * g.z + b.z;
    o.w = (x.w - mu) * rs * g.w + b.w;
    st4(g_vn + (size_t)r * HVV + d0, o);
}

// ---------------- vis_proj GEMM: (2048x1024) @ (1024x1024) + bias ----------------
// BM=BN=128, BK=8, 256 threads, 8x8 microtile.
__global__ __launch_bounds__(256, 2) void k_gemm_proj(const float* __restrict__ Wp,
                                                      const float* __restrict__ bp) {
    __shared__ float As[8][128];
    __shared__ float Bs[8][128];
    const int t = threadIdx.x;
    const int tx = t & 15, ty = t >> 4;
    const int c0 = blockIdx.x * 128;    // N tile
    const int r0 = blockIdx.y * 128;    // M tile
    const int am = t >> 1, ak = (t & 1) * 4;
    const int bk = t >> 5, bn = (t & 31) * 4;
    const float* aptr = g_vn + (size_t)(r0 + am) * HVV + ak;
    const float* bptr = Wp + (size_t)bk * DD + c0 + bn;

    float acc[8][8];
#pragma unroll
    for (int i = 0; i < 8; i++)
#pragma unroll
        for (int j = 0; j < 8; j++) acc[i][j] = 0.f;

    float4 av = ld4(aptr);
    float4 bv = ld4(bptr);
    for (int k0 = 0; k0 < HVV; k0 += 8) {
        __syncthreads();
        As[ak + 0][am] = av.x; As[ak + 1][am] = av.y;
        As[ak + 2][am] = av.z; As[ak + 3][am] = av.w;
        st4(&Bs[bk][bn], bv);
        __syncthreads();
        if (k0 + 8 < HVV) {
            av = ld4(aptr + k0 + 8);
            bv = ld4(bptr + (size_t)(k0 + 8) * DD);
        }
#pragma unroll
        for (int k = 0; k < 8; k++) {
            float a[8], b[8];
            *(float4*)&a[0] = ld4(&As[k][ty * 4]);
            *(float4*)&a[4] = ld4(&As[k][64 + ty * 4]);
            *(float4*)&b[0] = ld4(&Bs[k][tx * 4]);
            *(float4*)&b[4] = ld4(&Bs[k][64 + tx * 4]);
#pragma unroll
            for (int i = 0; i < 8; i++)
#pragma unroll
                for (int j = 0; j < 8; j++)
                    acc[i][j] = fmaf(a[i], b[j], acc[i][j]);
        }
    }
#pragma unroll
    for (int i = 0; i < 8; i++) {
        int ri = r0 + ((i < 4) ? ty * 4 + i : 64 + ty * 4 + (i - 4));
#pragma unroll
        for (int j = 0; j < 8; j++) {
            int cj = c0 + ((j < 4) ? tx * 4 + j : 64 + tx * 4 + (j - 4));
            g_vp[(size_t)ri * DD + cj] = acc[i][j] + bp[cj];
        }
    }
}

// ---------------- placeholder ranks ----------------
__global__ void k_rank(const int* __restrict__ ids) {
    int b = blockIdx.x, t = threadIdx.x;
    __shared__ int sc[256];
    int base = b * STK + t * 4;
    int f[4]; int loc = 0;
#pragma unroll
    for (int q = 0; q < 4; q++) {
        f[q] = (ids[base + q] == PLACE) ? 1 : 0;
        loc += f[q];
    }
    sc[t] = loc; __syncthreads();
    if (t == 0) {
        int run = 0;
        for (int i = 0; i < 256; i++) { int c = sc[i]; sc[i] = run; run += c; }
    }
    __syncthreads();
    int r = sc[t];
#pragma unroll
    for (int q = 0; q < 4; q++) {
        int id = ids[base + q];
        int src = id;
        if (f[q]) {
            if (r < 128) src = -(r + 1);
            r++;
        }
        g_src[base + q] = src;
    }
}

// ---------------- build text_emb ----------------
__global__ void k_fill(const float* __restrict__ emb) {
    int r = blockIdx.x;
    int d0 = threadIdx.x * 4;
    int src = g_src[r];
    float4 o;
    if (src < 0) {
        int c = -src - 1;
        int b = r >> 10;
        const float* p = g_vp + (size_t)(b * SVV + 2 * c) * DD + d0;
        float4 x = ld4(p);
        float4 y = ld4(p + DD);
        o.x = 0.5f * (x.x + y.x); o.y = 0.5f * (x.y + y.y);
        o.z = 0.5f * (x.z + y.z); o.w = 0.5f * (x.w + y.w);
    } else {
        o = ld4(emb + (size_t)src * DD + d0);
    }
    st4(g_text + (size_t)r * DD + d0, o);
}

// ---------------- per-batch sums for contrastive ----------------
__global__ void k_sums(const int* __restrict__ ids, const int* __restrict__ am) {
    int b = blockIdx.x;
    int d0 = threadIdx.x * 4;
    float4 ts = make_float4(0.f, 0.f, 0.f, 0.f);
    int cnt = 0;
    for (int s = 0; s < STK; s++) {
        int id = ids[b * STK + s];
        int a = am[b * STK + s];
        bool mk = (a != 0) && (id != PLACE);
        if (mk) {
            if (threadIdx.x == 0) cnt++;
            float4 x = ld4(g_text + (size_t)(b * STK + s) * DD + d0);
            ts.x += x.x; ts.y += x.y; ts.z += x.z; ts.w += x.w;
        }
    }
    float4 vs = make_float4(0.f, 0.f, 0.f, 0.f);
    for (int s = 0; s < SVV; s++) {
        float4 x = ld4(g_vp + (size_t)(b * SVV + s) * DD + d0);
        vs.x += x.x; vs.y += x.y; vs.z += x.z; vs.w += x.w;
    }
    st4(g_txtsum + b * DD + d0, ts);
    st4(g_vissum + b * DD + d0, vs);
    if (threadIdx.x == 0) g_cnttxt[b] = cnt;
}

// ---------------- fused LM head: GEMM + online logsumexp ----------------
// grid (NCH, NROWT); each block: 128 rows x 1280 cols (10 tiles of 128), K=1024.
__global__ __launch_bounds__(256, 2) void k_lmhead(const float* __restrict__ Wlm) {
    __shared__ float As[8][128];
    __shared__ float Bs[8][128];
    const int t = threadIdx.x;
    const int tx = t & 15, ty = t >> 4;
    const int ch = blockIdx.x;
    const int r0 = blockIdx.y * 128;
    const int am = t >> 1, ak = (t & 1) * 4;
    const int bk = t >> 5, bn = (t & 31) * 4;
    const float* aptr = g_text + (size_t)(r0 + am) * DD + ak;

    float m8[8], s8[8];
#pragma unroll
    for (int i = 0; i < 8; i++) { m8[i] = -1e30f; s8[i] = 0.f; }

    for (int vt = 0; vt < 10; vt++) {
        const int v0 = ch * CW + vt * 128;
        const float* bptr = Wlm + (size_t)bk * VV + v0 + bn;
        float acc[8][8];
#pragma unroll
        for (int i = 0; i < 8; i++)
#pragma unroll
            for (int j = 0; j < 8; j++) acc[i][j] = 0.f;

        float4 av = ld4(aptr);
        float4 bv = ld4(bptr);
        for (int k0 = 0; k0 < DD; k0 += 8) {
            __syncthreads();
            As[ak + 0][am] = av.x; As[ak + 1][am] = av.y;
            As[ak + 2][am] = av.z; As[ak + 3][am] = av.w;
            st4(&Bs[bk][bn], bv);
            __syncthreads();
            if (k0 + 8 < DD) {
                av = ld4(aptr + k0 + 8);
                bv = ld4(bptr + (size_t)(k0 + 8) * VV);
            }
#pragma unroll
            for (int k = 0; k < 8; k++) {
                float a[8], b[8];
                *(float4*)&a[0] = ld4(&As[k][ty * 4]);
                *(float4*)&a[4] = ld4(&As[k][64 + ty * 4]);
                *(float4*)&b[0] = ld4(&Bs[k][tx * 4]);
                *(float4*)&b[4] = ld4(&Bs[k][64 + tx * 4]);
#pragma unroll
                for (int i = 0; i < 8; i++)
#pragma unroll
                    for (int j = 0; j < 8; j++)
                        acc[i][j] = fmaf(a[i], b[j], acc[i][j]);
            }
        }
        // online softmax update (per thread-row over its 8 cols)
#pragma unroll
        for (int i = 0; i < 8; i++) {
            float tmax = acc[i][0];
#pragma unroll
            for (int j = 1; j < 8; j++) tmax = fmaxf(tmax, acc[i][j]);
            float mn = fmaxf(m8[i], tmax);
            float ss = 0.f;
#pragma unroll
            for (int j = 0; j < 8; j++) ss += __expf(acc[i][j] - mn);
            s8[i] = s8[i] * __expf(m8[i] - mn) + ss;
            m8[i] = mn;
        }
    }

    // reduce across the 16 lanes (same ty) sharing each row
#pragma unroll
    for (int i = 0; i < 8; i++) {
        float m = m8[i], s = s8[i];
#pragma unroll
        for (int off = 8; off > 0; off >>= 1) {
            float mo = __shfl_xor_sync(0xffffffffu, m, off);
            float so = __shfl_xor_sync(0xffffffffu, s, off);
            float mn = fmaxf(m, mo);
            s = s * __expf(m - mn) + so * __expf(mo - mn);
            m = mn;
        }
        if (tx == 0) {
            int ri = r0 + ((i < 4) ? ty * 4 + i : 64 + ty * 4 + (i - 4));
            g_pm[ch * ROWS + ri] = m;
            g_ps[ch * ROWS + ri] = s;
        }
    }
}

// ---------------- merge partials + label logit ----------------
__global__ void k_merge(const float* __restrict__ Wlm, const int* __restrict__ labels) {
    int gw = (blockIdx.x * blockDim.x + threadIdx.x) >> 5;
    int lane = threadIdx.x & 31;
    if (gw >= ROWS) return;
    int r = gw;
    int b = r >> 10, s = r & 1023;
    if (s == STK - 1) { if (lane == 0) g_ll[r] = 0.f; return; }

    float m = -1e30f, sm = 0.f;
    if (lane < NCH) { m = g_pm[lane * ROWS + r]; sm = g_ps[lane * ROWS + r]; }
#pragma unroll
    for (int off = 16; off > 0; off >>= 1) {
        float mo = __shfl_xor_sync(0xffffffffu, m, off);
        float so = __shfl_xor_sync(0xffffffffu, sm, off);
        float mn = fmaxf(m, mo);
        sm = sm * __expf(m - mn) + so * __expf(mo - mn);
        m = mn;
    }
    float lse = m + logf(sm);

    int label = labels[b * STK + s + 1];
    const float* trow = g_text + (size_t)r * DD;
    float dot = 0.f;
    for (int k = lane; k < DD; k += 32)
        dot = fmaf(trow[k], Wlm[(size_t)k * VV + label], dot);
#pragma unroll
    for (int off = 16; off > 0; off >>= 1)
        dot += __shfl_xor_sync(0xffffffffu, dot, off);
    if (lane == 0) g_ll[r] = lse - dot;
}

// ---------------- final losses ----------------
__global__ void k_final(float* __restrict__ out) {
    __shared__ float red[256];
    __shared__ float sh_sv2[NB], sh_st2[NB], shG[NB * NB];
    int t = threadIdx.x;

    // lm loss sum (deterministic tree reduce)
    float p = 0.f;
    for (int r = t; r < ROWS; r += 256)
        if ((r & 1023) != STK - 1) p += g_ll[r];
    red[t] = p; __syncthreads();
    for (int o = 128; o > 0; o >>= 1) { if (t < o) red[t] += red[t + o]; __syncthreads(); }
    float lmsum = red[0]; __syncthreads();

    for (int b = 0; b < NB; b++) {
        float a = 0.f, c = 0.f;
        for (int d = t; d < DD; d += 256) {
            float v = g_vissum[b * DD + d]; a += v * v;
            float w = g_txtsum[b * DD + d]; c += w * w;
        }
        red[t] = a; __syncthreads();
        for (int o = 128; o > 0; o >>= 1) { if (t < o) red[t] += red[t + o]; __syncthreads(); }
        if (t == 0) sh_sv2[b] = red[0];
        __syncthreads();
        red[t] = c; __syncthreads();
        for (int o = 128; o > 0; o >>= 1) { if (t < o) red[t] += red[t + o]; __syncthreads(); }
        if (t == 0) sh_st2[b] = red[0];
        __syncthreads();
    }
    for (int i = 0; i < NB; i++)
        for (int j = 0; j < NB; j++) {
            float a = 0.f;
            for (int d = t; d < DD; d += 256)
                a += g_vissum[i * DD + d] * g_txtsum[j * DD + d];
            red[t] = a; __syncthreads();
            for (int o = 128; o > 0; o >>= 1) { if (t < o) red[t] += red[t + o]; __syncthreads(); }
            if (t == 0) shG[i * NB + j] = red[0];
            __syncthreads();
        }

    if (t == 0) {
        float inv_v[NB], inv_t[NB];
        for (int b = 0; b < NB; b++) {
            float nv = fmaxf(sqrtf(sh_sv2[b]) / (float)SVV, 1e-12f);
            inv_v[b] = 1.f / ((float)SVV * nv);
            float den = fmaxf((float)g_cnttxt[b], 1.f);
            float nt = fmaxf(sqrtf(sh_st2[b]) / den, 1e-12f);
            inv_t[b] = 1.f / (den * nt);
        }
        float sim[NB][NB];
        for (int i = 0; i < NB; i++)
            for (int j = 0; j < NB; j++)
                sim[i][j] = shG[i * NB + j] * inv_v[i] * inv_t[j] / TEMP;
        float ce1 = 0.f, ce2 = 0.f;
        for (int i = 0; i < NB; i++) {
            float mx = sim[i][0];
            for (int j = 1; j < NB; j++) mx = fmaxf(mx, sim[i][j]);
            float su = 0.f;
            for (int j = 0; j < NB; j++) su += expf(sim[i][j] - mx);
            ce1 += (mx + logf(su)) - sim[i][i];
        }
        for (int j = 0; j < NB; j++) {
            float mx = sim[0][j];
            for (int i = 1; i < NB; i++) mx = fmaxf(mx, sim[i][j]);
            float su = 0.f;
            for (int i = 0; i < NB; i++) su += expf(sim[i][j] - mx);
            ce2 += (mx + logf(su)) - sim[j][j];
        }
        float cont = 0.5f * (ce1 / (float)NB + ce2 / (float)NB);
        float lm = lmsum / (float)(NB * (STK - 1));
        out[0] = lm + 0.5f * cont;
        out[1] = lm;
        out[2] = cont;
    }
}

// ---------------- launch ----------------
extern "C" void kernel_launch(void* const* d_in, const int* in_sizes, int n_in,
                              void* d_out, int out_size) {
    const float* vis    = (const float*)d_in[0];
    const int*   ids    = (const int*)d_in[1];
    const int*   am     = (const int*)d_in[2];
    const int*   labels = (const int*)d_in[3];
    const float* gamma  = (const float*)d_in[4];
    const float* beta   = (const float*)d_in[5];
    const float* Wp     = (const float*)d_in[6];
    const float* bp     = (const float*)d_in[7];
    const float* emb    = (const float*)d_in[8];
    const float* Wlm    = (const float*)d_in[9];
    float* out = (float*)d_out;

    k_lnstats<<<VROWS, 256>>>(vis);
    k_lnapply<<<VROWS, 256>>>(vis, gamma, beta);
    k_gemm_proj<<<dim3(8, 16), 256>>>(Wp, bp);
    k_rank<<<NB, 256>>>(ids);
    k_fill<<<ROWS, 256>>>(emb);
    k_sums<<<NB, 256>>>(ids, am);
    k_lmhead<<<dim3(NCH, NROWT), 256>>>(Wlm);
    k_merge<<<1024, 256>>>(Wlm, labels);
    k_final<<<1, 256>>>(out);
}

// round 6
// speedup vs baseline: 6.5706x; 6.5706x over previous
#include <cuda_runtime.h>
#include <cuda_bf16.h>
#include <math.h>
#include <stdint.h>

// ---------------- problem constants ----------------
#define PLACE   31999
#define NB      8
#define STK     1024
#define SVV     256
#define HVV     1024
#define DD      1024
#define VV      32000
#define ROWS    8192      // NB*STK
#define VROWS   2048      // NB*SVV
#define BMT     256       // LM-head CTA tile M
#define BNT     128       // LM-head CTA tile N
#define NRT     32        // ROWS/BMT
#define NVT     250       // VV/BNT
#define NCHP    250       // partial sets (one per vocab tile)
#define LNEPS   1e-5f
#define TEMP    0.07f

// ---------------- scratch (device globals; no cudaMalloc allowed) ----------------
__device__ float g_mu[VROWS];
__device__ float g_rs[VROWS];
__device__ __align__(16) float g_vn[VROWS * HVV];
__device__ __align__(16) float g_vp[VROWS * DD];
__device__ int   g_src[ROWS];
__device__ int   g_cnttxt[NB];
__device__ __align__(16) float g_text[ROWS * DD];
__device__ __align__(16) __nv_bfloat16 g_text16[ROWS * DD];
__device__ __align__(16) __nv_bfloat16 g_wlmT[(size_t)VV * DD];   // W_lm^T bf16 [v][d]
__device__ float g_pm[(size_t)NCHP * ROWS];
__device__ float g_ps[(size_t)NCHP * ROWS];
__device__ float g_ll[ROWS];
__device__ __align__(16) float g_txtsum[NB * DD];
__device__ __align__(16) float g_vissum[NB * DD];
__device__ __align__(16) float g_tpart[NB * 16 * DD];
__device__ __align__(16) float g_vpart[NB * 16 * DD];

// ---------------- helpers ----------------
__device__ __forceinline__ float4 ld4(const float* p) { return *(const float4*)p; }
__device__ __forceinline__ void st4(float* p, float4 v) { *(float4*)p = v; }

__device__ __forceinline__ uint32_t smem_u32(const void* p) {
    uint32_t a;
    asm("{ .reg .u64 t; cvta.to.shared.u64 t, %1; cvt.u32.u64 %0, t; }" : "=r"(a) : "l"(p));
    return a;
}

__device__ __forceinline__ void cp16(uint32_t dst, const void* src) {
    asm volatile("cp.async.cg.shared.global [%0], [%1], 16;" :: "r"(dst), "l"(src));
}
#define CP_COMMIT() asm volatile("cp.async.commit_group;" ::: "memory")
#define CP_WAIT1()  asm volatile("cp.async.wait_group 1;" ::: "memory")

__device__ __forceinline__ void ldsm4(uint32_t& r0, uint32_t& r1, uint32_t& r2, uint32_t& r3,
                                      uint32_t addr) {
    asm volatile("ldmatrix.sync.aligned.m8n8.x4.shared.b16 {%0,%1,%2,%3}, [%4];"
                 : "=r"(r0), "=r"(r1), "=r"(r2), "=r"(r3) : "r"(addr));
}

__device__ __forceinline__ void mma16816(float& c0, float& c1, float& c2, float& c3,
                                         uint32_t a0, uint32_t a1, uint32_t a2, uint32_t a3,
                                         uint32_t b0, uint32_t b1) {
    asm volatile("mma.sync.aligned.m16n8k16.row.col.f32.bf16.bf16.f32 "
                 "{%0,%1,%2,%3}, {%4,%5,%6,%7}, {%8,%9}, {%0,%1,%2,%3};"
                 : "+f"(c0), "+f"(c1), "+f"(c2), "+f"(c3)
                 : "r"(a0), "r"(a1), "r"(a2), "r"(a3), "r"(b0), "r"(b1));
}

// ---------------- LN stats ----------------
__global__ void k_lnstats(const float* __restrict__ vis) {
    int r = blockIdx.x, t = threadIdx.x;
    __shared__ float sa[256], sb[256];
    float s = 0.f, s2 = 0.f;
    for (int i = t; i < HVV; i += 256) {
        float v = vis[(size_t)r * HVV + i];
        s += v; s2 += v * v;
    }
    sa[t] = s; sb[t] = s2; __syncthreads();
    for (int o = 128; o > 0; o >>= 1) {
        if (t < o) { sa[t] += sa[t + o]; sb[t] += sb[t + o]; }
        __syncthreads();
    }
    if (t == 0) {
        float mu = sa[0] / (float)HVV;
        float var = sb[0] / (float)HVV - mu * mu;
        g_mu[r] = mu;
        g_rs[r] = rsqrtf(var + LNEPS);
    }
}

// ---------------- LN apply ----------------
__global__ void k_lnapply(const float* __restrict__ vis,
                          const float* __restrict__ gamma,
                          const float* __restrict__ beta) {
    int r = blockIdx.x;
    int d0 = threadIdx.x * 4;
    float mu = g_mu[r], rs = g_rs[r];
    float4 x = ld4(vis + (size_t)r * HVV + d0);
    float4 g = ld4(gamma + d0);
    float4 b = ld4(beta + d0);
    float4 o;
    o.x = (x.x - mu) * rs * g.x + b.x;
    o.y = (x.y - mu) * rs * g.y + b.y;
    o.z = (x.z - mu) * rs * g.z + b.z;
    o.w = (x.w - mu) * rs * g.w + b.w;
    st4(g_vn + (size_t)r * HVV + d0, o);
}

// ---------------- vis_proj GEMM (SIMT fp32, 4.3 GF) ----------------
__global__ __launch_bounds__(256, 2) void k_gemm_proj(const float* __restrict__ Wp,
                                                      const float* __restrict__ bp) {
    __shared__ float As[8][128];
    __shared__ float Bs[8][128];
    const int t = threadIdx.x;
    const int tx = t & 15, ty = t >> 4;
    const int c0 = blockIdx.x * 128;
    const int r0 = blockIdx.y * 128;
    const int am = t >> 1, ak = (t & 1) * 4;
    const int bk = t >> 5, bn = (t & 31) * 4;
    const float* aptr = g_vn + (size_t)(r0 + am) * HVV + ak;
    const float* bptr = Wp + (size_t)bk * DD + c0 + bn;

    float acc[8][8];
#pragma unroll
    for (int i = 0; i < 8; i++)
#pragma unroll
        for (int j = 0; j < 8; j++) acc[i][j] = 0.f;

    float4 av = ld4(aptr);
    float4 bv = ld4(bptr);
    for (int k0 = 0; k0 < HVV; k0 += 8) {
        __syncthreads();
        As[ak + 0][am] = av.x; As[ak + 1][am] = av.y;
        As[ak + 2][am] = av.z; As[ak + 3][am] = av.w;
        st4(&Bs[bk][bn], bv);
        __syncthreads();
        if (k0 + 8 < HVV) {
            av = ld4(aptr + k0 + 8);
            bv = ld4(bptr + (size_t)(k0 + 8) * DD);
        }
#pragma unroll
        for (int k = 0; k < 8; k++) {
            float a[8], b[8];
            *(float4*)&a[0] = ld4(&As[k][ty * 4]);
            *(float4*)&a[4] = ld4(&As[k][64 + ty * 4]);
            *(float4*)&b[0] = ld4(&Bs[k][tx * 4]);
            *(float4*)&b[4] = ld4(&Bs[k][64 + tx * 4]);
#pragma unroll
            for (int i = 0; i < 8; i++)
#pragma unroll
                for (int j = 0; j < 8; j++)
                    acc[i][j] = fmaf(a[i], b[j], acc[i][j]);
        }
    }
#pragma unroll
    for (int i = 0; i < 8; i++) {
        int ri = r0 + ((i < 4) ? ty * 4 + i : 64 + ty * 4 + (i - 4));
#pragma unroll
        for (int j = 0; j < 8; j++) {
            int cj = c0 + ((j < 4) ? tx * 4 + j : 64 + tx * 4 + (j - 4));
            g_vp[(size_t)ri * DD + cj] = acc[i][j] + bp[cj];
        }
    }
}

// ---------------- transpose + convert W_lm: [1024][32000] f32 -> [32000][1024] bf16 ----------------
__global__ void k_wt(const float* __restrict__ Wlm) {
    __shared__ float tile[32][33];
    int tx = threadIdx.x & 31, ty = threadIdx.x >> 5;   // 32 x 8
    int x0 = blockIdx.x * 32;    // vocab
    int y0 = blockIdx.y * 32;    // d
#pragma unroll
    for (int j = 0; j < 4; j++)
        tile[ty + 8 * j][tx] = Wlm[(size_t)(y0 + ty + 8 * j) * VV + x0 + tx];
    __syncthreads();
#pragma unroll
    for (int j = 0; j < 4; j++)
        g_wlmT[(size_t)(x0 + ty + 8 * j) * DD + y0 + tx] =
            __float2bfloat16_rn(tile[tx][ty + 8 * j]);
}

// ---------------- placeholder ranks + text-token counts ----------------
__global__ void k_rank(const int* __restrict__ ids, const int* __restrict__ am) {
    int b = blockIdx.x, t = threadIdx.x;
    __shared__ int sc[256];
    __shared__ int sc2[256];
    int base = b * STK + t * 4;
    int f[4]; int loc = 0, loc2 = 0;
#pragma unroll
    for (int q = 0; q < 4; q++) {
        int id = ids[base + q];
        f[q] = (id == PLACE) ? 1 : 0;
        loc += f[q];
        if (am[base + q] != 0 && id != PLACE) loc2++;
    }
    sc[t] = loc; sc2[t] = loc2; __syncthreads();
    if (t == 0) {
        int run = 0, tot = 0;
        for (int i = 0; i < 256; i++) { int c = sc[i]; sc[i] = run; run += c; tot += sc2[i]; }
        g_cnttxt[b] = tot;
    }
    __syncthreads();
    int r = sc[t];
#pragma unroll
    for (int q = 0; q < 4; q++) {
        int id = ids[base + q];
        int src = id;
        if (f[q]) {
            if (r < 128) src = -(r + 1);
            r++;
        }
        g_src[base + q] = src;
    }
}

// ---------------- build text_emb (fp32 + bf16) ----------------
__global__ void k_fill(const float* __restrict__ emb) {
    int r = blockIdx.x;
    int d0 = threadIdx.x * 4;
    int src = g_src[r];
    float4 o;
    if (src < 0) {
        int c = -src - 1;
        int b = r >> 10;
        const float* p = g_vp + (size_t)(b * SVV + 2 * c) * DD + d0;
        float4 x = ld4(p);
        float4 y = ld4(p + DD);
        o.x = 0.5f * (x.x + y.x); o.y = 0.5f * (x.y + y.y);
        o.z = 0.5f * (x.z + y.z); o.w = 0.5f * (x.w + y.w);
    } else {
        o = ld4(emb + (size_t)src * DD + d0);
    }
    st4(g_text + (size_t)r * DD + d0, o);
    __nv_bfloat16* t16 = g_text16 + (size_t)r * DD + d0;
    t16[0] = __float2bfloat16_rn(o.x);
    t16[1] = __float2bfloat16_rn(o.y);
    t16[2] = __float2bfloat16_rn(o.z);
    t16[3] = __float2bfloat16_rn(o.w);
}

// ---------------- per-batch partial sums ----------------
__global__ void k_sums1(const int* __restrict__ ids, const int* __restrict__ am) {
    int b = blockIdx.y, sl = blockIdx.x;
    int d0 = threadIdx.x * 4;
    float4 ts = make_float4(0.f, 0.f, 0.f, 0.f);
    for (int i = 0; i < 64; i++) {
        int s = sl * 64 + i;
        int id = ids[b * STK + s];
        int a = am[b * STK + s];
        if (a != 0 && id != PLACE) {
            float4 x = ld4(g_text + (size_t)(b * STK + s) * DD + d0);
            ts.x += x.x; ts.y += x.y; ts.z += x.z; ts.w += x.w;
        }
    }
    float4 vs = make_float4(0.f, 0.f, 0.f, 0.f);
    for (int i = 0; i < 16; i++) {
        int r = b * SVV + sl * 16 + i;
        float4 x = ld4(g_vp + (size_t)r * DD + d0);
        vs.x += x.x; vs.y += x.y; vs.z += x.z; vs.w += x.w;
    }
    st4(g_tpart + (size_t)(b * 16 + sl) * DD + d0, ts);
    st4(g_vpart + (size_t)(b * 16 + sl) * DD + d0, vs);
}

__global__ void k_sums2() {
    int b = blockIdx.x;
    int d0 = threadIdx.x * 4;
    float4 ts = make_float4(0.f, 0.f, 0.f, 0.f);
    float4 vs = make_float4(0.f, 0.f, 0.f, 0.f);
    for (int sl = 0; sl < 16; sl++) {
        float4 x = ld4(g_tpart + (size_t)(b * 16 + sl) * DD + d0);
        ts.x += x.x; ts.y += x.y; ts.z += x.z; ts.w += x.w;
        float4 y = ld4(g_vpart + (size_t)(b * 16 + sl) * DD + d0);
        vs.x += y.x; vs.y += y.y; vs.z += y.z; vs.w += y.w;
    }
    st4(g_txtsum + b * DD + d0, ts);
    st4(g_vissum + b * DD + d0, vs);
}

// ---------------- fused LM head via mma.sync (HMMA bf16, base sm_100 ISA) ----------------
// CTA tile 256(M) x 128(N), K=1024 in 16 chunks of 64. 512 threads = 16 warps (4M x 4N),
// warp tile 64x32, acc in registers. 3-stage cp.async ring:
//   stage s: A 256x128B @ s*49152, B 128x128B @ s*49152+32768.  Total 144KB.
// xor swizzle (seg ^ row&7) keeps ldmatrix conflict-free.
#define STG_SZ   49152
#define SM_TOTAL (3 * STG_SZ)

__global__ __launch_bounds__(512, 1) void k_lmhead_mma() {
    extern __shared__ char sm[];
    const uint32_t smb = smem_u32(sm);
    const int t = threadIdx.x;
    const int wid = t >> 5, lane = t & 31;
    const int wm = wid >> 2, wn = wid & 3;     // warp tile: rows wm*64.., cols wn*32..
    const int r0 = blockIdx.x * BMT;           // row tile (fast dim -> wave shares B via L2)
    const int n0 = blockIdx.y * BNT;           // vocab tile
    const int vt = blockIdx.y;

    // ---- loader lambda (cp.async 16B) ----
    auto load_chunk = [&](int c) {
        const uint32_t sA = smb + (c % 3) * STG_SZ;
        const uint32_t sB = sA + 32768;
        const int kb = c * 64;   // K offset (bf16 elems)
#pragma unroll
        for (int i = 0; i < 4; i++) {             // A: 2048 x 16B
            int u = t + i * 512;
            int row = u >> 3, q = u & 7;
            const void* src = g_text16 + (size_t)(r0 + row) * DD + kb + q * 8;
            cp16(sA + row * 128 + ((q ^ (row & 7)) << 4), src);
        }
#pragma unroll
        for (int i = 0; i < 2; i++) {             // B: 1024 x 16B
            int u = t + i * 512;
            int row = u >> 3, q = u & 7;
            const void* src = g_wlmT + (size_t)(n0 + row) * DD + kb + q * 8;
            cp16(sB + row * 128 + ((q ^ (row & 7)) << 4), src);
        }
        CP_COMMIT();
    };

    float acc[4][4][4];
#pragma unroll
    for (int i = 0; i < 4; i++)
#pragma unroll
        for (int j = 0; j < 4; j++)
#pragma unroll
            for (int q = 0; q < 4; q++) acc[i][j][q] = 0.f;

    load_chunk(0);
    load_chunk(1);

    // ldmatrix lane-address components (constant across chunks)
    const int lsub = lane >> 3;                 // matrix index 0..3
    const int l7 = lane & 7;
    // A x4: rows base + (lsub&1)*8 + l7 ; ksegs: ks*2 + (lsub>>1)
    const int a_row_off = ((lsub & 1) << 3) + l7;
    const int a_kseg_off = lsub >> 1;
    // B x4 (two n-subs): rows nbase + ((lsub>>1)<<3) + l7 ; kseg: ks*2 + (lsub&1)
    const int b_row_off = (((lsub >> 1) & 1) << 3) + l7;
    const int b_kseg_off = lsub & 1;

    for (int c = 0; c < 16; ++c) {
        CP_WAIT1();
        __syncthreads();
        if (c + 2 < 16) load_chunk(c + 2);
        else CP_COMMIT();                        // keep group count schedule uniform

        const uint32_t sA = smb + (c % 3) * STG_SZ;
        const uint32_t sB = sA + 32768;

#pragma unroll
        for (int ks = 0; ks < 4; ks++) {
            uint32_t a[4][4], b[4][2];
            // A frags: 4 m-subtiles
#pragma unroll
            for (int ms = 0; ms < 4; ms++) {
                int row = wm * 64 + ms * 16 + a_row_off;
                int kseg = ks * 2 + a_kseg_off;
                uint32_t addr = sA + row * 128 + (((kseg) ^ (row & 7)) << 4);
                ldsm4(a[ms][0], a[ms][1], a[ms][2], a[ms][3], addr);
            }
            // B frags: n-subs {0,1} and {2,3} via two x4 loads
#pragma unroll
            for (int np = 0; np < 2; np++) {
                int row = wn * 32 + np * 16 + b_row_off;
                int kseg = ks * 2 + b_kseg_off;
                uint32_t addr = sB + row * 128 + (((kseg) ^ (row & 7)) << 4);
                uint32_t r0r, r1r, r2r, r3r;
                ldsm4(r0r, r1r, r2r, r3r, addr);
                b[np * 2 + 0][0] = r0r; b[np * 2 + 0][1] = r1r;
                b[np * 2 + 1][0] = r2r; b[np * 2 + 1][1] = r3r;
            }
#pragma unroll
            for (int ms = 0; ms < 4; ms++)
#pragma unroll
                for (int ns = 0; ns < 4; ns++)
                    mma16816(acc[ms][ns][0], acc[ms][ns][1], acc[ms][ns][2], acc[ms][ns][3],
                             a[ms][0], a[ms][1], a[ms][2], a[ms][3],
                             b[ns][0], b[ns][1]);
        }
        __syncthreads();
    }

    // ---- epilogue: online (m, s) from register accumulators ----
    // c-frag: reg0=(row,col), reg1=(row,col+1), reg2=(row+8,col), reg3=(row+8,col+1)
    // with row = lane>>2, col = (lane&3)*2 within each m16n8 tile.
    float* sp_m = (float*)sm;          // [256][4]
    float* sp_s = sp_m + 1024;         // [256][4]
    __syncthreads();                   // all compute done before smem reuse

#pragma unroll
    for (int ms = 0; ms < 4; ms++) {
#pragma unroll
        for (int hh = 0; hh < 2; hh++) {         // row or row+8
            float mx = -1e30f;
#pragma unroll
            for (int ns = 0; ns < 4; ns++) {
                mx = fmaxf(mx, acc[ms][ns][hh * 2 + 0]);
                mx = fmaxf(mx, acc[ms][ns][hh * 2 + 1]);
            }
            // combine across the 4 lanes sharing this row (lane&3 varies)
            float se = 0.f;
            {
                float m1 = mx;
#pragma unroll
                for (int off = 1; off <= 2; off <<= 1)
                    m1 = fmaxf(m1, __shfl_xor_sync(0xffffffffu, m1, off));
                // m1 = row max over 32 cols
#pragma unroll
                for (int ns = 0; ns < 4; ns++) {
                    se += __expf(acc[ms][ns][hh * 2 + 0] - m1);
                    se += __expf(acc[ms][ns][hh * 2 + 1] - m1);
                }
#pragma unroll
                for (int off = 1; off <= 2; off <<= 1)
                    se += __shfl_xor_sync(0xffffffffu, se, off);
                mx = m1;
            }
            if ((lane & 3) == 0) {
                int row = wm * 64 + ms * 16 + hh * 8 + (lane >> 2);
                sp_m[row * 4 + wn] = mx;
                sp_s[row * 4 + wn] = se;
            }
        }
    }
    __syncthreads();
    if (t < 256) {
        float m = -1e30f;
#pragma unroll
        for (int j = 0; j < 4; j++) m = fmaxf(m, sp_m[t * 4 + j]);
        float s = 0.f;
#pragma unroll
        for (int j = 0; j < 4; j++) s += sp_s[t * 4 + j] * __expf(sp_m[t * 4 + j] - m);
        size_t ci = (size_t)vt * ROWS + r0 + t;
        g_pm[ci] = m;
        g_ps[ci] = s;
    }
}

// ---------------- merge partials + label logit ----------------
__global__ void k_merge(const int* __restrict__ labels) {
    int gw = (blockIdx.x * blockDim.x + threadIdx.x) >> 5;
    int lane = threadIdx.x & 31;
    if (gw >= ROWS) return;
    int r = gw;
    int b = r >> 10, s = r & 1023;
    if (s == STK - 1) { if (lane == 0) g_ll[r] = 0.f; return; }

    float m = -1e30f, sm = 0.f;
    for (int c = lane; c < NCHP; c += 32) {
        float mo = g_pm[(size_t)c * ROWS + r];
        float so = g_ps[(size_t)c * ROWS + r];
        float mn = fmaxf(m, mo);
        sm = sm * __expf(m - mn) + so * __expf(mo - mn);
        m = mn;
    }
#pragma unroll
    for (int off = 16; off > 0; off >>= 1) {
        float mo = __shfl_xor_sync(0xffffffffu, m, off);
        float so = __shfl_xor_sync(0xffffffffu, sm, off);
        float mn = fmaxf(m, mo);
        sm = sm * __expf(m - mn) + so * __expf(mo - mn);
        m = mn;
    }
    float lse = m + logf(sm);

    int label = labels[b * STK + s + 1];
    const __nv_bfloat16* trow = g_text16 + (size_t)r * DD;
    const __nv_bfloat16* wrow = g_wlmT + (size_t)label * DD;
    float dot = 0.f;
    for (int k = lane; k < DD; k += 32)
        dot = fmaf(__bfloat162float(trow[k]), __bfloat162float(wrow[k]), dot);
#pragma unroll
    for (int off = 16; off > 0; off >>= 1)
        dot += __shfl_xor_sync(0xffffffffu, dot, off);
    if (lane == 0) g_ll[r] = lse - dot;
}

// ---------------- final losses ----------------
__global__ void k_final(float* __restrict__ out) {
    __shared__ float red[256];
    __shared__ float sh_sv2[NB], sh_st2[NB], shG[NB * NB];
    int t = threadIdx.x;

    float p = 0.f;
    for (int r = t; r < ROWS; r += 256)
        if ((r & 1023) != STK - 1) p += g_ll[r];
    red[t] = p; __syncthreads();
    for (int o = 128; o > 0; o >>= 1) { if (t < o) red[t] += red[t + o]; __syncthreads(); }
    float lmsum = red[0]; __syncthreads();

    for (int b = 0; b < NB; b++) {
        float a = 0.f, c = 0.f;
        for (int d = t; d < DD; d += 256) {
            float v = g_vissum[b * DD + d]; a += v * v;
            float w = g_txtsum[b * DD + d]; c += w * w;
        }
        red[t] = a; __syncthreads();
        for (int o = 128; o > 0; o >>= 1) { if (t < o) red[t] += red[t + o]; __syncthreads(); }
        if (t == 0) sh_sv2[b] = red[0];
        __syncthreads();
        red[t] = c; __syncthreads();
        for (int o = 128; o > 0; o >>= 1) { if (t < o) red[t] += red[t + o]; __syncthreads(); }
        if (t == 0) sh_st2[b] = red[0];
        __syncthreads();
    }
    for (int i = 0; i < NB; i++)
        for (int j = 0; j < NB; j++) {
            float a = 0.f;
            for (int d = t; d < DD; d += 256)
                a += g_vissum[i * DD + d] * g_txtsum[j * DD + d];
            red[t] = a; __syncthreads();
            for (int o = 128; o > 0; o >>= 1) { if (t < o) red[t] += red[t + o]; __syncthreads(); }
            if (t == 0) shG[i * NB + j] = red[0];
            __syncthreads();
        }

    if (t == 0) {
        float inv_v[NB], inv_t[NB];
        for (int b = 0; b < NB; b++) {
            float nv = fmaxf(sqrtf(sh_sv2[b]) / (float)SVV, 1e-12f);
            inv_v[b] = 1.f / ((float)SVV * nv);
            float den = fmaxf((float)g_cnttxt[b], 1.f);
            float nt = fmaxf(sqrtf(sh_st2[b]) / den, 1e-12f);
            inv_t[b] = 1.f / (den * nt);
        }
        float sim[NB][NB];
        for (int i = 0; i < NB; i++)
            for (int j = 0; j < NB; j++)
                sim[i][j] = shG[i * NB + j] * inv_v[i] * inv_t[j] / TEMP;
        float ce1 = 0.f, ce2 = 0.f;
        for (int i = 0; i < NB; i++) {
            float mx = sim[i][0];
            for (int j = 1; j < NB; j++) mx = fmaxf(mx, sim[i][j]);
            float su = 0.f;
            for (int j = 0; j < NB; j++) su += expf(sim[i][j] - mx);
            ce1 += (mx + logf(su)) - sim[i][i];
        }
        for (int j = 0; j < NB; j++) {
            float mx = sim[0][j];
            for (int i = 1; i < NB; i++) mx = fmaxf(mx, sim[i][j]);
            float su = 0.f;
            for (int i = 0; i < NB; i++) su += expf(sim[i][j] - mx);
            ce2 += (mx + logf(su)) - sim[j][j];
        }
        float cont = 0.5f * (ce1 / (float)NB + ce2 / (float)NB);
        float lm = lmsum / (float)(NB * (STK - 1));
        out[0] = lm + 0.5f * cont;
        out[1] = lm;
        out[2] = cont;
    }
}

// ---------------- launch ----------------
extern "C" void kernel_launch(void* const* d_in, const int* in_sizes, int n_in,
                              void* d_out, int out_size) {
    const float* vis    = (const float*)d_in[0];
    const int*   ids    = (const int*)d_in[1];
    const int*   am     = (const int*)d_in[2];
    const int*   labels = (const int*)d_in[3];
    const float* gamma  = (const float*)d_in[4];
    const float* beta   = (const float*)d_in[5];
    const float* Wp     = (const float*)d_in[6];
    const float* bp     = (const float*)d_in[7];
    const float* emb    = (const float*)d_in[8];
    const float* Wlm    = (const float*)d_in[9];
    float* out = (float*)d_out;

    cudaFuncSetAttribute(k_lmhead_mma, cudaFuncAttributeMaxDynamicSharedMemorySize, SM_TOTAL);

    k_wt<<<dim3(VV / 32, DD / 32), 256>>>(Wlm);
    k_lnstats<<<VROWS, 256>>>(vis);
    k_lnapply<<<VROWS, 256>>>(vis, gamma, beta);
    k_gemm_proj<<<dim3(8, 16), 256>>>(Wp, bp);
    k_rank<<<NB, 256>>>(ids, am);
    k_fill<<<ROWS, 256>>>(emb);
    k_sums1<<<dim3(16, NB), 256>>>(ids, am);
    k_sums2<<<NB, 256>>>();
    k_lmhead_mma<<<dim3(NRT, NVT), 512, SM_TOTAL>>>();
    k_merge<<<1024, 256>>>(labels);
    k_final<<<1, 256>>>(out);
}